// round 2
// baseline (speedup 1.0000x reference)
#include <cuda_runtime.h>
#include <math.h>

#define NN 50000
#define NE 800000
#define H 128
#define NRAD 16
#define EDP 276            // padded edge-feature stride (275 used), 276*4 % 16 == 0
#define TE 32              // edges per block
#define TN 32              // nodes per block
#define PI_F 3.14159265358979f

// Scratch (no dynamic allocation allowed)
__device__ float g_agg[NN * H];
__device__ float g_cnt[NN];
__device__ float g_delta[NN * 3];

__device__ __forceinline__ float silu_f(float v) {
    return v / (1.f + __expf(-v));
}

__global__ void zero_kernel() {
    int i = blockIdx.x * blockDim.x + threadIdx.x;
    int s = gridDim.x * blockDim.x;
    for (int idx = i; idx < NN * H; idx += s) g_agg[idx] = 0.f;
    for (int idx = i; idx < NN; idx += s) g_cnt[idx] = 0.f;
    for (int idx = i; idx < NN * 3; idx += s) g_delta[idx] = 0.f;
}

__global__ __launch_bounds__(256) void edge_kernel(
    const float* __restrict__ x, const float* __restrict__ pos,
    const float* __restrict__ charge, const float* __restrict__ edge_attr,
    const int* __restrict__ edge_index,
    const float* __restrict__ We1, const float* __restrict__ be1,
    const float* __restrict__ g1, const float* __restrict__ bt1,
    const float* __restrict__ We2, const float* __restrict__ be2,
    const float* __restrict__ Wc1, const float* __restrict__ bc1,
    const float* __restrict__ Wc2, const float* __restrict__ bc2)
{
    __shared__ float s_buf[TE * EDP];   // phase1: ef[32][276]; later h[32][128] @0, eh[32][128] @4096, c1[32][64] @0
    __shared__ float s_gate[TE];
    __shared__ float s_unit[TE][3];
    __shared__ int   s_src[TE];
    __shared__ float s_coord[TE];

    const int tid = threadIdx.x;
    const int e0 = blockIdx.x * TE;

    // ---- per-edge scalar features (32 threads) ----
    if (tid < TE) {
        const int e = e0 + tid;
        const int src = edge_index[e];
        const int dst = edge_index[NE + e];
        s_src[tid] = src;
        const float rx = pos[dst * 3 + 0] - pos[src * 3 + 0];
        const float ry = pos[dst * 3 + 1] - pos[src * 3 + 1];
        const float rz = pos[dst * 3 + 2] - pos[src * 3 + 2];
        const float dist = sqrtf(rx * rx + ry * ry + rz * rz + 1e-8f);
        const float inv = 1.f / dist;     // dist >= 1e-4 so clip(1e-6) is a no-op
        s_unit[tid][0] = rx * inv; s_unit[tid][1] = ry * inv; s_unit[tid][2] = rz * inv;

        const float4 ea = *(const float4*)&edge_attr[e * 4];
        float ca = cosf(ea.x);
        float p2 = 0.5f * (3.f * ca * ca - 1.f);
        float p3 = (5.f * ca * p2 - 2.f * ca) * (1.f / 3.f);
        float a_score = 0.25f * (1.f + fabsf(ca) + fabsf(p2) + fabsf(p3)) * ea.z;
        float cd = cosf(ea.y);
        float q2 = 0.5f * (3.f * cd * cd - 1.f);
        float q3 = (5.f * cd * q2 - 2.f * cd) * (1.f / 3.f);
        float d_score = 0.25f * (1.f + fabsf(cd) + fabsf(q2) + fabsf(q3)) * ea.w;
        float gate = fminf(fmaxf(1.f + 0.6f * (a_score + d_score), 0.35f), 2.5f);
        s_gate[tid] = gate;

        const float qs = charge[src], qd = charge[dst];
        float* row = &s_buf[tid * EDP];
        const float gi = gate * inv;
        #pragma unroll
        for (int i = 0; i < NRAD; i++) {
            float f = (float)(i + 1) * (PI_F / 5.0f);
            row[2 * H + i] = sinf(f * dist) * gi;       // sin(f*d)/d * gate
        }
        row[272] = dist * 0.2f * gate;
        row[273] = qs * qd * gate;
        row[274] = fabsf(qs - qd) * gate;
    }

    // ---- gather x[src], x[dst] rows (float4, coalesced) ----
    for (int idx = tid; idx < TE * 32; idx += 256) {
        const int e = idx >> 5, j4 = idx & 31;
        const int src = edge_index[e0 + e];
        const int dst = edge_index[NE + e0 + e];
        *(float4*)&s_buf[e * EDP + j4 * 4]     = *(const float4*)&x[src * H + j4 * 4];
        *(float4*)&s_buf[e * EDP + H + j4 * 4] = *(const float4*)&x[dst * H + j4 * 4];
    }
    __syncthreads();

    const int j = tid & (H - 1);
    const int g = tid >> 7;          // 0/1 -> edge half
    const int ebase = g * 16;
    float* const s_h  = s_buf;               // [32][128]
    float* const s_eh = s_buf + TE * H;      // [32][128]  (8832 >= 8192)
    float* const s_c1 = s_buf;               // [32][64]   (h dead by then)

    // ---- GEMM1: h = silu(ef @ We1 + be1) ----
    float acc[16];
    #pragma unroll
    for (int e = 0; e < 16; e++) acc[e] = 0.f;
    for (int k = 0; k < 272; k += 4) {
        const float w0 = We1[(k + 0) * H + j];
        const float w1 = We1[(k + 1) * H + j];
        const float w2 = We1[(k + 2) * H + j];
        const float w3 = We1[(k + 3) * H + j];
        #pragma unroll
        for (int e = 0; e < 16; e++) {
            const float4 v = *(const float4*)&s_buf[(ebase + e) * EDP + k];
            acc[e] = fmaf(v.x, w0, fmaf(v.y, w1, fmaf(v.z, w2, fmaf(v.w, w3, acc[e]))));
        }
    }
    for (int k = 272; k < 275; k++) {
        const float w = We1[k * H + j];
        #pragma unroll
        for (int e = 0; e < 16; e++)
            acc[e] = fmaf(s_buf[(ebase + e) * EDP + k], w, acc[e]);
    }
    const float b1 = be1[j];
    __syncthreads();                 // everyone done reading ef
    #pragma unroll
    for (int e = 0; e < 16; e++)
        s_h[(ebase + e) * H + j] = silu_f(acc[e] + b1);
    __syncthreads();

    // ---- LayerNorm(h) with g1/bt1 : warp per 4 edges ----
    const int lane = tid & 31, wrp = tid >> 5;
    {
        const float ga = g1[lane], gb = g1[lane + 32], gc = g1[lane + 64], gd = g1[lane + 96];
        const float ba = bt1[lane], bb = bt1[lane + 32], bcv = bt1[lane + 64], bd = bt1[lane + 96];
        #pragma unroll
        for (int q = 0; q < 4; q++) {
            const int e = wrp * 4 + q;
            float v0 = s_h[e * H + lane], v1 = s_h[e * H + lane + 32];
            float v2 = s_h[e * H + lane + 64], v3 = s_h[e * H + lane + 96];
            float s1 = v0 + v1 + v2 + v3;
            float s2 = v0 * v0 + v1 * v1 + v2 * v2 + v3 * v3;
            #pragma unroll
            for (int o = 16; o; o >>= 1) {
                s1 += __shfl_xor_sync(0xffffffffu, s1, o);
                s2 += __shfl_xor_sync(0xffffffffu, s2, o);
            }
            const float m = s1 * (1.f / 128.f);
            const float var = s2 * (1.f / 128.f) - m * m;
            const float rstd = rsqrtf(var + 1e-5f);
            s_h[e * H + lane]      = (v0 - m) * rstd * ga + ba;
            s_h[e * H + lane + 32] = (v1 - m) * rstd * gb + bb;
            s_h[e * H + lane + 64] = (v2 - m) * rstd * gc + bcv;
            s_h[e * H + lane + 96] = (v3 - m) * rstd * gd + bd;
        }
    }
    __syncthreads();

    // ---- GEMM2: eh = silu(h @ We2 + be2) ----
    #pragma unroll
    for (int e = 0; e < 16; e++) acc[e] = 0.f;
    for (int k = 0; k < H; k += 4) {
        const float w0 = We2[(k + 0) * H + j];
        const float w1 = We2[(k + 1) * H + j];
        const float w2 = We2[(k + 2) * H + j];
        const float w3 = We2[(k + 3) * H + j];
        #pragma unroll
        for (int e = 0; e < 16; e++) {
            const float4 v = *(const float4*)&s_h[(ebase + e) * H + k];
            acc[e] = fmaf(v.x, w0, fmaf(v.y, w1, fmaf(v.z, w2, fmaf(v.w, w3, acc[e]))));
        }
    }
    const float b2 = be2[j];
    #pragma unroll
    for (int e = 0; e < 16; e++)
        s_eh[(ebase + e) * H + j] = silu_f(acc[e] + b2);   // disjoint region, no hazard
    __syncthreads();

    // ---- GEMM3: c1 = silu(eh @ Wc1 + bc1), then coord = c1 @ Wc2 + bc2 ----
    {
        const int j2 = tid & 63, g2 = tid >> 6;
        float a3[8];
        #pragma unroll
        for (int i = 0; i < 8; i++) a3[i] = 0.f;
        for (int k = 0; k < H; k += 4) {
            const float w0 = Wc1[(k + 0) * 64 + j2];
            const float w1 = Wc1[(k + 1) * 64 + j2];
            const float w2 = Wc1[(k + 2) * 64 + j2];
            const float w3 = Wc1[(k + 3) * 64 + j2];
            #pragma unroll
            for (int i = 0; i < 8; i++) {
                const float4 v = *(const float4*)&s_eh[(g2 * 8 + i) * H + k];
                a3[i] = fmaf(v.x, w0, fmaf(v.y, w1, fmaf(v.z, w2, fmaf(v.w, w3, a3[i]))));
            }
        }
        const float b3 = bc1[j2];
        #pragma unroll
        for (int i = 0; i < 8; i++)
            s_c1[(g2 * 8 + i) * 64 + j2] = silu_f(a3[i] + b3);  // overlays dead h region
    }
    __syncthreads();
    {
        const float wa = Wc2[lane], wb = Wc2[lane + 32];
        #pragma unroll
        for (int q = 0; q < 4; q++) {
            const int e = wrp * 4 + q;
            float t = s_c1[e * 64 + lane] * wa + s_c1[e * 64 + lane + 32] * wb;
            #pragma unroll
            for (int o = 16; o; o >>= 1) t += __shfl_xor_sync(0xffffffffu, t, o);
            if (lane == 0) s_coord[e] = t + bc2[0];
        }
    }
    __syncthreads();

    // ---- scatter: agg += eh; cnt += 1; delta += unit*coord*gate ----
    for (int idx = tid; idx < TE * H; idx += 256) {
        const int e = idx >> 7, jj = idx & (H - 1);
        atomicAdd(&g_agg[s_src[e] * H + jj], s_eh[e * H + jj]);
    }
    if (tid < TE) {
        const int src = s_src[tid];
        const float f = s_coord[tid] * s_gate[tid];
        atomicAdd(&g_cnt[src], 1.0f);
        atomicAdd(&g_delta[src * 3 + 0], s_unit[tid][0] * f);
        atomicAdd(&g_delta[src * 3 + 1], s_unit[tid][1] * f);
        atomicAdd(&g_delta[src * 3 + 2], s_unit[tid][2] * f);
    }
}

__global__ __launch_bounds__(256) void node_kernel(
    const float* __restrict__ x, const float* __restrict__ pos,
    const float* __restrict__ Wn, const float* __restrict__ bn,
    const float* __restrict__ gn, const float* __restrict__ btn,
    float* __restrict__ out)
{
    __shared__ float s_cat[TN * 260];   // cat[32][256] padded to 260; later y[32][128]
    const int tid = threadIdx.x;
    const int n0 = blockIdx.x * TN;

    for (int idx = tid; idx < TN * 64; idx += 256) {
        const int nl = idx >> 6, j4 = idx & 63;
        const int n = n0 + nl;
        float4 v = make_float4(0.f, 0.f, 0.f, 0.f);
        if (n < NN) {
            if (j4 < 32) {
                v = *(const float4*)&x[n * H + j4 * 4];
            } else {
                const float c = fmaxf(g_cnt[n], 1.f);
                const float iv = 1.f / c;
                v = *(const float4*)&g_agg[n * H + (j4 - 32) * 4];
                v.x *= iv; v.y *= iv; v.z *= iv; v.w *= iv;
            }
        }
        *(float4*)&s_cat[nl * 260 + j4 * 4] = v;
    }
    __syncthreads();

    const int j = tid & (H - 1), g = tid >> 7;
    float acc[16];
    #pragma unroll
    for (int e = 0; e < 16; e++) acc[e] = 0.f;
    for (int k = 0; k < 256; k += 4) {
        const float w0 = Wn[(k + 0) * H + j];
        const float w1 = Wn[(k + 1) * H + j];
        const float w2 = Wn[(k + 2) * H + j];
        const float w3 = Wn[(k + 3) * H + j];
        #pragma unroll
        for (int e = 0; e < 16; e++) {
            const float4 v = *(const float4*)&s_cat[(g * 16 + e) * 260 + k];
            acc[e] = fmaf(v.x, w0, fmaf(v.y, w1, fmaf(v.z, w2, fmaf(v.w, w3, acc[e]))));
        }
    }
    const float b = bn[j];
    __syncthreads();
    float* const s_y = s_cat;
    #pragma unroll
    for (int e = 0; e < 16; e++)
        s_y[(g * 16 + e) * H + j] = silu_f(acc[e] + b);
    __syncthreads();

    const int lane = tid & 31, wrp = tid >> 5;
    const float ga = gn[lane], gb = gn[lane + 32], gc = gn[lane + 64], gd = gn[lane + 96];
    const float ba = btn[lane], bb = btn[lane + 32], bcv = btn[lane + 64], bd = btn[lane + 96];
    #pragma unroll
    for (int q = 0; q < 4; q++) {
        const int nl = wrp * 4 + q;
        const int n = n0 + nl;
        float v0 = s_y[nl * H + lane], v1 = s_y[nl * H + lane + 32];
        float v2 = s_y[nl * H + lane + 64], v3 = s_y[nl * H + lane + 96];
        float s1 = v0 + v1 + v2 + v3;
        float s2 = v0 * v0 + v1 * v1 + v2 * v2 + v3 * v3;
        #pragma unroll
        for (int o = 16; o; o >>= 1) {
            s1 += __shfl_xor_sync(0xffffffffu, s1, o);
            s2 += __shfl_xor_sync(0xffffffffu, s2, o);
        }
        const float m = s1 * (1.f / 128.f);
        const float var = s2 * (1.f / 128.f) - m * m;
        const float rstd = rsqrtf(var + 1e-5f);
        if (n < NN) {
            out[n * H + lane]      = x[n * H + lane]      + (v0 - m) * rstd * ga + ba;
            out[n * H + lane + 32] = x[n * H + lane + 32] + (v1 - m) * rstd * gb + bb;
            out[n * H + lane + 64] = x[n * H + lane + 64] + (v2 - m) * rstd * gc + bcv;
            out[n * H + lane + 96] = x[n * H + lane + 96] + (v3 - m) * rstd * gd + bd;
        }
    }
    if (tid < TN) {
        const int n = n0 + tid;
        if (n < NN) {
            const float c = fmaxf(g_cnt[n], 1.f);
            const float s = 0.1f / c;
            out[NN * H + n * 3 + 0] = pos[n * 3 + 0] + s * g_delta[n * 3 + 0];
            out[NN * H + n * 3 + 1] = pos[n * 3 + 1] + s * g_delta[n * 3 + 1];
            out[NN * H + n * 3 + 2] = pos[n * 3 + 2] + s * g_delta[n * 3 + 2];
        }
    }
}

extern "C" void kernel_launch(void* const* d_in, const int* in_sizes, int n_in,
                              void* d_out, int out_size) {
    const float* x         = (const float*)d_in[0];
    const float* pos       = (const float*)d_in[1];
    const float* charge    = (const float*)d_in[2];
    const float* edge_attr = (const float*)d_in[3];
    const int*   edge_index= (const int*)d_in[4];
    const float* We1 = (const float*)d_in[5];
    const float* be1 = (const float*)d_in[6];
    const float* g1  = (const float*)d_in[7];
    const float* bt1 = (const float*)d_in[8];
    const float* We2 = (const float*)d_in[9];
    const float* be2 = (const float*)d_in[10];
    const float* Wn  = (const float*)d_in[11];
    const float* bn  = (const float*)d_in[12];
    const float* gn  = (const float*)d_in[13];
    const float* btn = (const float*)d_in[14];
    const float* Wc1 = (const float*)d_in[15];
    const float* bc1 = (const float*)d_in[16];
    const float* Wc2 = (const float*)d_in[17];
    const float* bc2 = (const float*)d_in[18];
    float* out = (float*)d_out;

    zero_kernel<<<1024, 256>>>();
    edge_kernel<<<NE / TE, 256>>>(x, pos, charge, edge_attr, edge_index,
                                  We1, be1, g1, bt1, We2, be2, Wc1, bc1, Wc2, bc2);
    node_kernel<<<(NN + TN - 1) / TN, 256>>>(x, pos, Wn, bn, gn, btn, out);
}

// round 3
// speedup vs baseline: 1.1366x; 1.1366x over previous
#include <cuda_runtime.h>
#include <math.h>

#define NN 50000
#define NE 800000
#define H 128
#define NRAD 16
#define EDP 276            // padded edge-feature stride (275 used), 276*4 % 16 == 0
#define TE 32              // edges per block
#define TN 32              // nodes per block
#define PI_F 3.14159265358979f

typedef unsigned long long u64t;

// Scratch (no dynamic allocation allowed)
__device__ float g_agg[NN * H];
__device__ float g_cnt[NN];
__device__ float g_delta[NN * 3];

__device__ __forceinline__ float silu_f(float v) {
    return v / (1.f + __expf(-v));
}

// packed fp32x2 FMA: d = a * b + d (elementwise on (lo,hi))
__device__ __forceinline__ void fma2(u64t& d, u64t a, u64t b) {
    asm("fma.rn.f32x2 %0, %1, %2, %0;" : "+l"(d) : "l"(a), "l"(b));
}
__device__ __forceinline__ u64t pack2(float lo, float hi) {
    u64t d; asm("mov.b64 %0, {%1, %2};" : "=l"(d) : "f"(lo), "f"(hi)); return d;
}
__device__ __forceinline__ float hadd2(u64t d) {
    float lo, hi; asm("mov.b64 {%0, %1}, %2;" : "=f"(lo), "=f"(hi) : "l"(d));
    return lo + hi;
}

__global__ void zero_kernel() {
    int i = blockIdx.x * blockDim.x + threadIdx.x;
    int s = gridDim.x * blockDim.x;
    for (int idx = i; idx < NN * H; idx += s) g_agg[idx] = 0.f;
    for (int idx = i; idx < NN; idx += s) g_cnt[idx] = 0.f;
    for (int idx = i; idx < NN * 3; idx += s) g_delta[idx] = 0.f;
}

__global__ __launch_bounds__(256) void edge_kernel(
    const float* __restrict__ x, const float* __restrict__ pos,
    const float* __restrict__ charge, const float* __restrict__ edge_attr,
    const int* __restrict__ edge_index,
    const float* __restrict__ We1, const float* __restrict__ be1,
    const float* __restrict__ g1, const float* __restrict__ bt1,
    const float* __restrict__ We2, const float* __restrict__ be2,
    const float* __restrict__ Wc1, const float* __restrict__ bc1,
    const float* __restrict__ Wc2, const float* __restrict__ bc2)
{
    __shared__ __align__(16) float s_buf[TE * EDP];  // ef[32][276]; later h[32][128]@0, eh[32][128]@4096, c1[32][64]@0
    __shared__ float s_gate[TE];
    __shared__ float s_unit[TE][3];
    __shared__ int   s_src[TE];
    __shared__ float s_coord[TE];

    const int tid = threadIdx.x;
    const int e0 = blockIdx.x * TE;

    // ---- per-edge scalar features (32 threads) ----
    if (tid < TE) {
        const int e = e0 + tid;
        const int src = edge_index[e];
        const int dst = edge_index[NE + e];
        s_src[tid] = src;
        const float rx = pos[dst * 3 + 0] - pos[src * 3 + 0];
        const float ry = pos[dst * 3 + 1] - pos[src * 3 + 1];
        const float rz = pos[dst * 3 + 2] - pos[src * 3 + 2];
        const float dist = sqrtf(rx * rx + ry * ry + rz * rz + 1e-8f);
        const float inv = 1.f / dist;
        s_unit[tid][0] = rx * inv; s_unit[tid][1] = ry * inv; s_unit[tid][2] = rz * inv;

        const float4 ea = *(const float4*)&edge_attr[e * 4];
        float ca = cosf(ea.x);
        float p2 = 0.5f * (3.f * ca * ca - 1.f);
        float p3 = (5.f * ca * p2 - 2.f * ca) * (1.f / 3.f);
        float a_score = 0.25f * (1.f + fabsf(ca) + fabsf(p2) + fabsf(p3)) * ea.z;
        float cd = cosf(ea.y);
        float q2 = 0.5f * (3.f * cd * cd - 1.f);
        float q3 = (5.f * cd * q2 - 2.f * cd) * (1.f / 3.f);
        float d_score = 0.25f * (1.f + fabsf(cd) + fabsf(q2) + fabsf(q3)) * ea.w;
        float gate = fminf(fmaxf(1.f + 0.6f * (a_score + d_score), 0.35f), 2.5f);
        s_gate[tid] = gate;

        const float qs = charge[src], qd = charge[dst];
        float* row = &s_buf[tid * EDP];
        const float gi = gate * inv;
        #pragma unroll
        for (int i = 0; i < NRAD; i++) {
            float f = (float)(i + 1) * (PI_F / 5.0f);
            row[2 * H + i] = sinf(f * dist) * gi;
        }
        row[272] = dist * 0.2f * gate;
        row[273] = qs * qd * gate;
        row[274] = fabsf(qs - qd) * gate;
        row[275] = 0.f;
    }

    // ---- gather x[src], x[dst] rows ----
    for (int idx = tid; idx < TE * 32; idx += 256) {
        const int e = idx >> 5, j4 = idx & 31;
        const int src = edge_index[e0 + e];
        const int dst = edge_index[NE + e0 + e];
        *(float4*)&s_buf[e * EDP + j4 * 4]     = *(const float4*)&x[src * H + j4 * 4];
        *(float4*)&s_buf[e * EDP + H + j4 * 4] = *(const float4*)&x[dst * H + j4 * 4];
    }
    __syncthreads();

    // thread -> 2 columns (jj, jj+64), 8 edges (group g)
    const int jj = tid & 63;
    const int g  = tid >> 6;          // 0..3
    const int eb = g * 8;
    float* const s_h  = s_buf;               // [32][128]
    float* const s_eh = s_buf + TE * H;      // [32][128]
    float* const s_c1 = s_buf;               // [32][64]

    // ---- GEMM1: h = silu(ef @ We1 + be1) ----  (packed over k-parity, 2 cols)
    u64t accA[8], accB[8];
    #pragma unroll
    for (int e = 0; e < 8; e++) { accA[e] = 0ull; accB[e] = 0ull; }
    for (int k = 0; k < 272; k += 4) {
        const float wA0 = We1[(k + 0) * H + jj],      wA1 = We1[(k + 1) * H + jj];
        const float wA2 = We1[(k + 2) * H + jj],      wA3 = We1[(k + 3) * H + jj];
        const float wB0 = We1[(k + 0) * H + jj + 64], wB1 = We1[(k + 1) * H + jj + 64];
        const float wB2 = We1[(k + 2) * H + jj + 64], wB3 = We1[(k + 3) * H + jj + 64];
        const u64t pA0 = pack2(wA0, wA1), pA1 = pack2(wA2, wA3);
        const u64t pB0 = pack2(wB0, wB1), pB1 = pack2(wB2, wB3);
        #pragma unroll
        for (int e = 0; e < 8; e++) {
            const ulonglong2 v = *(const ulonglong2*)&s_buf[(eb + e) * EDP + k];
            fma2(accA[e], v.x, pA0); fma2(accA[e], v.y, pA1);
            fma2(accB[e], v.x, pB0); fma2(accB[e], v.y, pB1);
        }
    }
    float aA[8], aB[8];
    #pragma unroll
    for (int e = 0; e < 8; e++) { aA[e] = hadd2(accA[e]); aB[e] = hadd2(accB[e]); }
    #pragma unroll
    for (int k = 272; k < 275; k++) {
        const float wA = We1[k * H + jj], wB = We1[k * H + jj + 64];
        #pragma unroll
        for (int e = 0; e < 8; e++) {
            const float v = s_buf[(eb + e) * EDP + k];
            aA[e] = fmaf(v, wA, aA[e]);
            aB[e] = fmaf(v, wB, aB[e]);
        }
    }
    const float b1A = be1[jj], b1B = be1[jj + 64];
    __syncthreads();                 // ef fully read
    #pragma unroll
    for (int e = 0; e < 8; e++) {
        s_h[(eb + e) * H + jj]      = silu_f(aA[e] + b1A);
        s_h[(eb + e) * H + jj + 64] = silu_f(aB[e] + b1B);
    }
    __syncthreads();

    // ---- LayerNorm(h) ----
    const int lane = tid & 31, wrp = tid >> 5;
    {
        const float ga = g1[lane], gb = g1[lane + 32], gc = g1[lane + 64], gd = g1[lane + 96];
        const float ba = bt1[lane], bb = bt1[lane + 32], bcv = bt1[lane + 64], bd = bt1[lane + 96];
        #pragma unroll
        for (int q = 0; q < 4; q++) {
            const int e = wrp * 4 + q;
            float v0 = s_h[e * H + lane], v1 = s_h[e * H + lane + 32];
            float v2 = s_h[e * H + lane + 64], v3 = s_h[e * H + lane + 96];
            float s1 = v0 + v1 + v2 + v3;
            float s2 = v0 * v0 + v1 * v1 + v2 * v2 + v3 * v3;
            #pragma unroll
            for (int o = 16; o; o >>= 1) {
                s1 += __shfl_xor_sync(0xffffffffu, s1, o);
                s2 += __shfl_xor_sync(0xffffffffu, s2, o);
            }
            const float m = s1 * (1.f / 128.f);
            const float var = s2 * (1.f / 128.f) - m * m;
            const float rstd = rsqrtf(var + 1e-5f);
            s_h[e * H + lane]      = (v0 - m) * rstd * ga + ba;
            s_h[e * H + lane + 32] = (v1 - m) * rstd * gb + bb;
            s_h[e * H + lane + 64] = (v2 - m) * rstd * gc + bcv;
            s_h[e * H + lane + 96] = (v3 - m) * rstd * gd + bd;
        }
    }
    __syncthreads();

    // ---- GEMM2: eh = silu(h @ We2 + be2) ----
    #pragma unroll
    for (int e = 0; e < 8; e++) { accA[e] = 0ull; accB[e] = 0ull; }
    for (int k = 0; k < H; k += 4) {
        const float wA0 = We2[(k + 0) * H + jj],      wA1 = We2[(k + 1) * H + jj];
        const float wA2 = We2[(k + 2) * H + jj],      wA3 = We2[(k + 3) * H + jj];
        const float wB0 = We2[(k + 0) * H + jj + 64], wB1 = We2[(k + 1) * H + jj + 64];
        const float wB2 = We2[(k + 2) * H + jj + 64], wB3 = We2[(k + 3) * H + jj + 64];
        const u64t pA0 = pack2(wA0, wA1), pA1 = pack2(wA2, wA3);
        const u64t pB0 = pack2(wB0, wB1), pB1 = pack2(wB2, wB3);
        #pragma unroll
        for (int e = 0; e < 8; e++) {
            const ulonglong2 v = *(const ulonglong2*)&s_h[(eb + e) * H + k];
            fma2(accA[e], v.x, pA0); fma2(accA[e], v.y, pA1);
            fma2(accB[e], v.x, pB0); fma2(accB[e], v.y, pB1);
        }
    }
    const float b2A = be2[jj], b2B = be2[jj + 64];
    #pragma unroll
    for (int e = 0; e < 8; e++) {
        s_eh[(eb + e) * H + jj]      = silu_f(hadd2(accA[e]) + b2A);  // disjoint region
        s_eh[(eb + e) * H + jj + 64] = silu_f(hadd2(accB[e]) + b2B);
    }
    __syncthreads();

    // ---- GEMM3: c1 = silu(eh @ Wc1 + bc1) ----  (2 cols of 64, 4 edges/thread)
    {
        const int j3 = tid & 31;
        const int g3 = tid >> 5;       // 0..7 -> 4 edges each
        const int eb3 = g3 * 4;
        u64t cA[4], cB[4];
        #pragma unroll
        for (int i = 0; i < 4; i++) { cA[i] = 0ull; cB[i] = 0ull; }
        for (int k = 0; k < H; k += 4) {
            const float wA0 = Wc1[(k + 0) * 64 + j3],      wA1 = Wc1[(k + 1) * 64 + j3];
            const float wA2 = Wc1[(k + 2) * 64 + j3],      wA3 = Wc1[(k + 3) * 64 + j3];
            const float wB0 = Wc1[(k + 0) * 64 + j3 + 32], wB1 = Wc1[(k + 1) * 64 + j3 + 32];
            const float wB2 = Wc1[(k + 2) * 64 + j3 + 32], wB3 = Wc1[(k + 3) * 64 + j3 + 32];
            const u64t pA0 = pack2(wA0, wA1), pA1 = pack2(wA2, wA3);
            const u64t pB0 = pack2(wB0, wB1), pB1 = pack2(wB2, wB3);
            #pragma unroll
            for (int i = 0; i < 4; i++) {
                const ulonglong2 v = *(const ulonglong2*)&s_eh[(eb3 + i) * H + k];
                fma2(cA[i], v.x, pA0); fma2(cA[i], v.y, pA1);
                fma2(cB[i], v.x, pB0); fma2(cB[i], v.y, pB1);
            }
        }
        const float b3A = bc1[j3], b3B = bc1[j3 + 32];
        #pragma unroll
        for (int i = 0; i < 4; i++) {
            s_c1[(eb3 + i) * 64 + j3]      = silu_f(hadd2(cA[i]) + b3A);  // overlays dead h
            s_c1[(eb3 + i) * 64 + j3 + 32] = silu_f(hadd2(cB[i]) + b3B);
        }
    }
    __syncthreads();

    // ---- coord = c1 @ Wc2 + bc2 ----
    {
        const float wa = Wc2[lane], wb = Wc2[lane + 32];
        #pragma unroll
        for (int q = 0; q < 4; q++) {
            const int e = wrp * 4 + q;
            float t = s_c1[e * 64 + lane] * wa + s_c1[e * 64 + lane + 32] * wb;
            #pragma unroll
            for (int o = 16; o; o >>= 1) t += __shfl_xor_sync(0xffffffffu, t, o);
            if (lane == 0) s_coord[e] = t + bc2[0];
        }
    }
    __syncthreads();

    // ---- scatter ----
    for (int idx = tid; idx < TE * H; idx += 256) {
        const int e = idx >> 7, jc = idx & (H - 1);
        atomicAdd(&g_agg[s_src[e] * H + jc], s_eh[e * H + jc]);
    }
    if (tid < TE) {
        const int src = s_src[tid];
        const float f = s_coord[tid] * s_gate[tid];
        atomicAdd(&g_cnt[src], 1.0f);
        atomicAdd(&g_delta[src * 3 + 0], s_unit[tid][0] * f);
        atomicAdd(&g_delta[src * 3 + 1], s_unit[tid][1] * f);
        atomicAdd(&g_delta[src * 3 + 2], s_unit[tid][2] * f);
    }
}

__global__ __launch_bounds__(256) void node_kernel(
    const float* __restrict__ x, const float* __restrict__ pos,
    const float* __restrict__ Wn, const float* __restrict__ bn,
    const float* __restrict__ gn, const float* __restrict__ btn,
    float* __restrict__ out)
{
    __shared__ __align__(16) float s_cat[TN * 260];   // cat[32][256] pad 260; later y[32][128]
    const int tid = threadIdx.x;
    const int n0 = blockIdx.x * TN;

    for (int idx = tid; idx < TN * 64; idx += 256) {
        const int nl = idx >> 6, j4 = idx & 63;
        const int n = n0 + nl;
        float4 v = make_float4(0.f, 0.f, 0.f, 0.f);
        if (n < NN) {
            if (j4 < 32) {
                v = *(const float4*)&x[n * H + j4 * 4];
            } else {
                const float c = fmaxf(g_cnt[n], 1.f);
                const float iv = 1.f / c;
                v = *(const float4*)&g_agg[n * H + (j4 - 32) * 4];
                v.x *= iv; v.y *= iv; v.z *= iv; v.w *= iv;
            }
        }
        *(float4*)&s_cat[nl * 260 + j4 * 4] = v;
    }
    __syncthreads();

    const int jj = tid & 63, g = tid >> 6;
    const int nb = g * 8;
    u64t accA[8], accB[8];
    #pragma unroll
    for (int e = 0; e < 8; e++) { accA[e] = 0ull; accB[e] = 0ull; }
    for (int k = 0; k < 256; k += 4) {
        const float wA0 = Wn[(k + 0) * H + jj],      wA1 = Wn[(k + 1) * H + jj];
        const float wA2 = Wn[(k + 2) * H + jj],      wA3 = Wn[(k + 3) * H + jj];
        const float wB0 = Wn[(k + 0) * H + jj + 64], wB1 = Wn[(k + 1) * H + jj + 64];
        const float wB2 = Wn[(k + 2) * H + jj + 64], wB3 = Wn[(k + 3) * H + jj + 64];
        const u64t pA0 = pack2(wA0, wA1), pA1 = pack2(wA2, wA3);
        const u64t pB0 = pack2(wB0, wB1), pB1 = pack2(wB2, wB3);
        #pragma unroll
        for (int e = 0; e < 8; e++) {
            const ulonglong2 v = *(const ulonglong2*)&s_cat[(nb + e) * 260 + k];
            fma2(accA[e], v.x, pA0); fma2(accA[e], v.y, pA1);
            fma2(accB[e], v.x, pB0); fma2(accB[e], v.y, pB1);
        }
    }
    const float bA = bn[jj], bB = bn[jj + 64];
    __syncthreads();
    float* const s_y = s_cat;
    #pragma unroll
    for (int e = 0; e < 8; e++) {
        s_y[(nb + e) * H + jj]      = silu_f(hadd2(accA[e]) + bA);
        s_y[(nb + e) * H + jj + 64] = silu_f(hadd2(accB[e]) + bB);
    }
    __syncthreads();

    const int lane = tid & 31, wrp = tid >> 5;
    const float ga = gn[lane], gb = gn[lane + 32], gc = gn[lane + 64], gd = gn[lane + 96];
    const float ba = btn[lane], bb = btn[lane + 32], bcv = btn[lane + 64], bd = btn[lane + 96];
    #pragma unroll
    for (int q = 0; q < 4; q++) {
        const int nl = wrp * 4 + q;
        const int n = n0 + nl;
        float v0 = s_y[nl * H + lane], v1 = s_y[nl * H + lane + 32];
        float v2 = s_y[nl * H + lane + 64], v3 = s_y[nl * H + lane + 96];
        float s1 = v0 + v1 + v2 + v3;
        float s2 = v0 * v0 + v1 * v1 + v2 * v2 + v3 * v3;
        #pragma unroll
        for (int o = 16; o; o >>= 1) {
            s1 += __shfl_xor_sync(0xffffffffu, s1, o);
            s2 += __shfl_xor_sync(0xffffffffu, s2, o);
        }
        const float m = s1 * (1.f / 128.f);
        const float var = s2 * (1.f / 128.f) - m * m;
        const float rstd = rsqrtf(var + 1e-5f);
        if (n < NN) {
            out[n * H + lane]      = x[n * H + lane]      + (v0 - m) * rstd * ga + ba;
            out[n * H + lane + 32] = x[n * H + lane + 32] + (v1 - m) * rstd * gb + bb;
            out[n * H + lane + 64] = x[n * H + lane + 64] + (v2 - m) * rstd * gc + bcv;
            out[n * H + lane + 96] = x[n * H + lane + 96] + (v3 - m) * rstd * gd + bd;
        }
    }
    if (tid < TN) {
        const int n = n0 + tid;
        if (n < NN) {
            const float c = fmaxf(g_cnt[n], 1.f);
            const float s = 0.1f / c;
            out[NN * H + n * 3 + 0] = pos[n * 3 + 0] + s * g_delta[n * 3 + 0];
            out[NN * H + n * 3 + 1] = pos[n * 3 + 1] + s * g_delta[n * 3 + 1];
            out[NN * H + n * 3 + 2] = pos[n * 3 + 2] + s * g_delta[n * 3 + 2];
        }
    }
}

extern "C" void kernel_launch(void* const* d_in, const int* in_sizes, int n_in,
                              void* d_out, int out_size) {
    const float* x         = (const float*)d_in[0];
    const float* pos       = (const float*)d_in[1];
    const float* charge    = (const float*)d_in[2];
    const float* edge_attr = (const float*)d_in[3];
    const int*   edge_index= (const int*)d_in[4];
    const float* We1 = (const float*)d_in[5];
    const float* be1 = (const float*)d_in[6];
    const float* g1  = (const float*)d_in[7];
    const float* bt1 = (const float*)d_in[8];
    const float* We2 = (const float*)d_in[9];
    const float* be2 = (const float*)d_in[10];
    const float* Wn  = (const float*)d_in[11];
    const float* bn  = (const float*)d_in[12];
    const float* gn  = (const float*)d_in[13];
    const float* btn = (const float*)d_in[14];
    const float* Wc1 = (const float*)d_in[15];
    const float* bc1 = (const float*)d_in[16];
    const float* Wc2 = (const float*)d_in[17];
    const float* bc2 = (const float*)d_in[18];
    float* out = (float*)d_out;

    zero_kernel<<<1024, 256>>>();
    edge_kernel<<<NE / TE, 256>>>(x, pos, charge, edge_attr, edge_index,
                                  We1, be1, g1, bt1, We2, be2, Wc1, bc1, Wc2, bc2);
    node_kernel<<<(NN + TN - 1) / TN, 256>>>(x, pos, Wn, bn, gn, btn, out);
}

// round 4
// speedup vs baseline: 1.3531x; 1.1905x over previous
#include <cuda_runtime.h>
#include <math.h>
#include <stdint.h>

#define NN 50000
#define NE 800000
#define H 128
#define NRAD 16
#define TE 32              // edges per block
#define TN 32              // nodes per block
#define EDP 284            // ef row stride (floats): 275 used, mod32=28 -> conflict-free frags
#define HS  132            // h/eh row stride: mod32=4 -> conflict-free frags
#define SBN 136            // weight chunk stride (N=128): mod32=8 -> conflict-free
#define SBN3 72            // weight chunk stride (N=64): mod32=8
#define PI_F 3.14159265358979f

// dynamic smem layout (bytes)
#define OFF_EF 0
#define SZ_EF  (TE * EDP * 4)              // 36352 ; eh overlays here later (TE*HS*4=16896)
#define OFF_H  SZ_EF                        // 36352
#define SZ_H   (TE * HS * 4)               // 16896
#define OFF_B  (OFF_H + SZ_H)              // 53248
#define SZ_B   (32 * SBN * 4)              // 17408
#define SMEM_EDGE (OFF_B + SZ_B)           // 70656

typedef unsigned long long u64t;

__device__ float g_agg[NN * H];
__device__ float g_cnt[NN];
__device__ float g_delta[NN * 3];

__device__ __forceinline__ float silu_f(float v) { return v / (1.f + __expf(-v)); }

__device__ __forceinline__ float tf32r(float f) {
    uint32_t u; asm("cvt.rna.tf32.f32 %0, %1;" : "=r"(u) : "f"(f));
    return __uint_as_float(u);
}
__device__ __forceinline__ uint32_t tf32u(float f) {
    uint32_t u; asm("cvt.rna.tf32.f32 %0, %1;" : "=r"(u) : "f"(f));
    return u;
}
__device__ __forceinline__ void mma_tf32(float* d, uint32_t a0, uint32_t a1, uint32_t a2,
                                         uint32_t a3, uint32_t b0, uint32_t b1) {
    asm("mma.sync.aligned.m16n8k8.row.col.f32.tf32.tf32.f32 "
        "{%0,%1,%2,%3},{%4,%5,%6,%7},{%8,%9},{%0,%1,%2,%3};"
        : "+f"(d[0]), "+f"(d[1]), "+f"(d[2]), "+f"(d[3])
        : "r"(a0), "r"(a1), "r"(a2), "r"(a3), "r"(b0), "r"(b1));
}

// packed fp32x2 helpers (node kernel)
__device__ __forceinline__ void fma2(u64t& d, u64t a, u64t b) {
    asm("fma.rn.f32x2 %0, %1, %2, %0;" : "+l"(d) : "l"(a), "l"(b));
}
__device__ __forceinline__ u64t pack2(float lo, float hi) {
    u64t d; asm("mov.b64 %0, {%1, %2};" : "=l"(d) : "f"(lo), "f"(hi)); return d;
}
__device__ __forceinline__ float hadd2(u64t d) {
    float lo, hi; asm("mov.b64 {%0, %1}, %2;" : "=f"(lo), "=f"(hi) : "l"(d));
    return lo + hi;
}

__global__ __launch_bounds__(256) void edge_kernel(
    const float* __restrict__ x, const float* __restrict__ pos,
    const float* __restrict__ charge, const float* __restrict__ edge_attr,
    const int* __restrict__ edge_index,
    const float* __restrict__ We1, const float* __restrict__ be1,
    const float* __restrict__ g1, const float* __restrict__ bt1,
    const float* __restrict__ We2, const float* __restrict__ be2,
    const float* __restrict__ Wc1, const float* __restrict__ bc1,
    const float* __restrict__ Wc2, const float* __restrict__ bc2)
{
    extern __shared__ __align__(16) char dyn_smem[];
    float* const ef   = (float*)(dyn_smem + OFF_EF);   // [32][284]
    float* const s_h  = (float*)(dyn_smem + OFF_H);    // [32][132]
    float* const s_eh = (float*)(dyn_smem + OFF_EF);   // [32][132] overlays ef
    float* const s_B  = (float*)(dyn_smem + OFF_B);    // [32][136] / [32][72]

    __shared__ float s_gate[TE];
    __shared__ float s_unit[TE][3];
    __shared__ int   s_src[TE];
    __shared__ float s_coord[TE];

    const int tid = threadIdx.x;
    const int e0 = blockIdx.x * TE;

    // ---- per-edge scalars ----
    if (tid < TE) {
        const int e = e0 + tid;
        const int src = edge_index[e];
        const int dst = edge_index[NE + e];
        s_src[tid] = src;
        const float rx = pos[dst * 3 + 0] - pos[src * 3 + 0];
        const float ry = pos[dst * 3 + 1] - pos[src * 3 + 1];
        const float rz = pos[dst * 3 + 2] - pos[src * 3 + 2];
        const float dist = sqrtf(rx * rx + ry * ry + rz * rz + 1e-8f);
        const float inv = 1.f / dist;
        s_unit[tid][0] = rx * inv; s_unit[tid][1] = ry * inv; s_unit[tid][2] = rz * inv;

        const float4 ea = *(const float4*)&edge_attr[e * 4];
        float ca = cosf(ea.x);
        float p2 = 0.5f * (3.f * ca * ca - 1.f);
        float p3 = (5.f * ca * p2 - 2.f * ca) * (1.f / 3.f);
        float a_score = 0.25f * (1.f + fabsf(ca) + fabsf(p2) + fabsf(p3)) * ea.z;
        float cd = cosf(ea.y);
        float q2 = 0.5f * (3.f * cd * cd - 1.f);
        float q3 = (5.f * cd * q2 - 2.f * cd) * (1.f / 3.f);
        float d_score = 0.25f * (1.f + fabsf(cd) + fabsf(q2) + fabsf(q3)) * ea.w;
        float gate = fminf(fmaxf(1.f + 0.6f * (a_score + d_score), 0.35f), 2.5f);
        s_gate[tid] = gate;
        s_coord[tid] = bc2[0];

        const float qs = charge[src], qd = charge[dst];
        float* row = &ef[tid * EDP];
        const float gi = gate * inv;
        #pragma unroll
        for (int i = 0; i < NRAD; i++) {
            float f = (float)(i + 1) * (PI_F / 5.0f);
            row[2 * H + i] = sinf(f * dist) * gi;
        }
        row[272] = dist * 0.2f * gate;
        row[273] = qs * qd * gate;
        row[274] = fabsf(qs - qd) * gate;
        #pragma unroll
        for (int i = 275; i < EDP; i++) row[i] = 0.f;
    }

    // ---- gather x[src], x[dst] into ef cols 0..255 ----
    for (int idx = tid; idx < TE * 32; idx += 256) {
        const int e = idx >> 5, j4 = idx & 31;
        const int src = edge_index[e0 + e];
        const int dst = edge_index[NE + e0 + e];
        *(float4*)&ef[e * EDP + j4 * 4]     = *(const float4*)&x[src * H + j4 * 4];
        *(float4*)&ef[e * EDP + H + j4 * 4] = *(const float4*)&x[dst * H + j4 * 4];
    }

    const int lane = tid & 31, w = tid >> 5;
    const int g = lane >> 2, tg = lane & 3;
    const int m0 = (w & 1) * 16;
    const int nb = (w >> 1) * 32;      // n-block (4 tiles of 8)
    const int kk = tid >> 3, q = tid & 7;

    float d[4][4];
    #pragma unroll
    for (int t = 0; t < 4; t++)
        #pragma unroll
        for (int i = 0; i < 4; i++) d[t][i] = 0.f;

    // ================= GEMM1: ef[32x280] @ We1[280x128] =================
    for (int c = 0; c < 9; c++) {
        __syncthreads();   // prev mma done / gather done (c==0)
        {
            const int k = c * 32 + kk;
            float* dstw = &s_B[kk * SBN + q * 16];
            if (k < 275) {
                const float* srcw = &We1[k * H + q * 16];
                #pragma unroll
                for (int i = 0; i < 4; i++) {
                    float4 v = *(const float4*)(srcw + i * 4);
                    v.x = tf32r(v.x); v.y = tf32r(v.y); v.z = tf32r(v.z); v.w = tf32r(v.w);
                    *(float4*)(dstw + i * 4) = v;
                }
            } else {
                const float4 z = make_float4(0.f, 0.f, 0.f, 0.f);
                #pragma unroll
                for (int i = 0; i < 4; i++) *(float4*)(dstw + i * 4) = z;
            }
        }
        __syncthreads();
        #pragma unroll
        for (int ks = 0; ks < 4; ks++) {
            const int sg = c * 4 + ks;
            if (sg >= 35) break;
            const int kg = sg * 8;          // global k (col in ef)
            const int kl = ks * 8;          // local row in s_B
            const uint32_t a0 = tf32u(ef[(m0 + g) * EDP + kg + tg]);
            const uint32_t a1 = tf32u(ef[(m0 + 8 + g) * EDP + kg + tg]);
            const uint32_t a2 = tf32u(ef[(m0 + g) * EDP + kg + 4 + tg]);
            const uint32_t a3 = tf32u(ef[(m0 + 8 + g) * EDP + kg + 4 + tg]);
            #pragma unroll
            for (int t = 0; t < 4; t++) {
                const uint32_t b0 = __float_as_uint(s_B[(kl + tg) * SBN + nb + t * 8 + g]);
                const uint32_t b1 = __float_as_uint(s_B[(kl + 4 + tg) * SBN + nb + t * 8 + g]);
                mma_tf32(d[t], a0, a1, a2, a3, b0, b1);
            }
        }
    }
    __syncthreads();

    // ---- epilogue1: silu(+be1) -> s_h ----
    #pragma unroll
    for (int t = 0; t < 4; t++) {
        const int col = nb + t * 8 + tg * 2;
        const float bb0 = be1[col], bb1 = be1[col + 1];
        s_h[(m0 + g) * HS + col]         = silu_f(d[t][0] + bb0);
        s_h[(m0 + g) * HS + col + 1]     = silu_f(d[t][1] + bb1);
        s_h[(m0 + 8 + g) * HS + col]     = silu_f(d[t][2] + bb0);
        s_h[(m0 + 8 + g) * HS + col + 1] = silu_f(d[t][3] + bb1);
    }
    __syncthreads();

    // ---- LayerNorm(h) : warp per 4 edges ----
    {
        const float ga = g1[lane], gb = g1[lane + 32], gc = g1[lane + 64], gd = g1[lane + 96];
        const float ba = bt1[lane], bb = bt1[lane + 32], bcv = bt1[lane + 64], bd = bt1[lane + 96];
        #pragma unroll
        for (int qq = 0; qq < 4; qq++) {
            const int e = w * 4 + qq;
            float v0 = s_h[e * HS + lane], v1 = s_h[e * HS + lane + 32];
            float v2 = s_h[e * HS + lane + 64], v3 = s_h[e * HS + lane + 96];
            float s1 = v0 + v1 + v2 + v3;
            float s2 = v0 * v0 + v1 * v1 + v2 * v2 + v3 * v3;
            #pragma unroll
            for (int o = 16; o; o >>= 1) {
                s1 += __shfl_xor_sync(0xffffffffu, s1, o);
                s2 += __shfl_xor_sync(0xffffffffu, s2, o);
            }
            const float m = s1 * (1.f / 128.f);
            const float var = s2 * (1.f / 128.f) - m * m;
            const float rstd = rsqrtf(var + 1e-5f);
            s_h[e * HS + lane]      = (v0 - m) * rstd * ga + ba;
            s_h[e * HS + lane + 32] = (v1 - m) * rstd * gb + bb;
            s_h[e * HS + lane + 64] = (v2 - m) * rstd * gc + bcv;
            s_h[e * HS + lane + 96] = (v3 - m) * rstd * gd + bd;
        }
    }

    // ================= GEMM2: h[32x128] @ We2[128x128] =================
    #pragma unroll
    for (int t = 0; t < 4; t++)
        #pragma unroll
        for (int i = 0; i < 4; i++) d[t][i] = 0.f;
    for (int c = 0; c < 4; c++) {
        __syncthreads();
        {
            const int k = c * 32 + kk;
            const float* srcw = &We2[k * H + q * 16];
            float* dstw = &s_B[kk * SBN + q * 16];
            #pragma unroll
            for (int i = 0; i < 4; i++) {
                float4 v = *(const float4*)(srcw + i * 4);
                v.x = tf32r(v.x); v.y = tf32r(v.y); v.z = tf32r(v.z); v.w = tf32r(v.w);
                *(float4*)(dstw + i * 4) = v;
            }
        }
        __syncthreads();
        #pragma unroll
        for (int ks = 0; ks < 4; ks++) {
            const int kg = c * 32 + ks * 8;
            const int kl = ks * 8;
            const uint32_t a0 = tf32u(s_h[(m0 + g) * HS + kg + tg]);
            const uint32_t a1 = tf32u(s_h[(m0 + 8 + g) * HS + kg + tg]);
            const uint32_t a2 = tf32u(s_h[(m0 + g) * HS + kg + 4 + tg]);
            const uint32_t a3 = tf32u(s_h[(m0 + 8 + g) * HS + kg + 4 + tg]);
            #pragma unroll
            for (int t = 0; t < 4; t++) {
                const uint32_t b0 = __float_as_uint(s_B[(kl + tg) * SBN + nb + t * 8 + g]);
                const uint32_t b1 = __float_as_uint(s_B[(kl + 4 + tg) * SBN + nb + t * 8 + g]);
                mma_tf32(d[t], a0, a1, a2, a3, b0, b1);
            }
        }
    }
    __syncthreads();

    // ---- epilogue2: eh = silu(+be2) -> s_eh (overlays dead ef) ----
    #pragma unroll
    for (int t = 0; t < 4; t++) {
        const int col = nb + t * 8 + tg * 2;
        const float bb0 = be2[col], bb1 = be2[col + 1];
        s_eh[(m0 + g) * HS + col]         = silu_f(d[t][0] + bb0);
        s_eh[(m0 + g) * HS + col + 1]     = silu_f(d[t][1] + bb1);
        s_eh[(m0 + 8 + g) * HS + col]     = silu_f(d[t][2] + bb0);
        s_eh[(m0 + 8 + g) * HS + col + 1] = silu_f(d[t][3] + bb1);
    }

    // ================= GEMM3: eh[32x128] @ Wc1[128x64] =================
    float d3[2][4];
    #pragma unroll
    for (int t = 0; t < 2; t++)
        #pragma unroll
        for (int i = 0; i < 4; i++) d3[t][i] = 0.f;
    const int nb3 = (w >> 1) * 16;
    for (int c = 0; c < 4; c++) {
        __syncthreads();   // also makes epilogue2 stores visible before mma
        {
            const int k = c * 32 + kk;
            const float* srcw = &Wc1[k * 64 + q * 8];
            float* dstw = &s_B[kk * SBN3 + q * 8];
            #pragma unroll
            for (int i = 0; i < 2; i++) {
                float4 v = *(const float4*)(srcw + i * 4);
                v.x = tf32r(v.x); v.y = tf32r(v.y); v.z = tf32r(v.z); v.w = tf32r(v.w);
                *(float4*)(dstw + i * 4) = v;
            }
        }
        __syncthreads();
        #pragma unroll
        for (int ks = 0; ks < 4; ks++) {
            const int kg = c * 32 + ks * 8;
            const int kl = ks * 8;
            const uint32_t a0 = tf32u(s_eh[(m0 + g) * HS + kg + tg]);
            const uint32_t a1 = tf32u(s_eh[(m0 + 8 + g) * HS + kg + tg]);
            const uint32_t a2 = tf32u(s_eh[(m0 + g) * HS + kg + 4 + tg]);
            const uint32_t a3 = tf32u(s_eh[(m0 + 8 + g) * HS + kg + 4 + tg]);
            #pragma unroll
            for (int t = 0; t < 2; t++) {
                const uint32_t b0 = __float_as_uint(s_B[(kl + tg) * SBN3 + nb3 + t * 8 + g]);
                const uint32_t b1 = __float_as_uint(s_B[(kl + 4 + tg) * SBN3 + nb3 + t * 8 + g]);
                mma_tf32(d3[t], a0, a1, a2, a3, b0, b1);
            }
        }
    }
    __syncthreads();

    // ---- epilogue3: coord = silu(+bc1) @ Wc2 (+bc2 via s_coord init) ----
    {
        float sA = 0.f, sB2 = 0.f;
        #pragma unroll
        for (int t = 0; t < 2; t++) {
            const int col = nb3 + t * 8 + tg * 2;
            const float w0 = Wc2[col], w1 = Wc2[col + 1];
            const float c0 = bc1[col], c1 = bc1[col + 1];
            sA  += silu_f(d3[t][0] + c0) * w0 + silu_f(d3[t][1] + c1) * w1;
            sB2 += silu_f(d3[t][2] + c0) * w0 + silu_f(d3[t][3] + c1) * w1;
        }
        atomicAdd(&s_coord[m0 + g], sA);
        atomicAdd(&s_coord[m0 + 8 + g], sB2);
    }
    __syncthreads();

    // ---- scatter ----
    for (int idx = tid; idx < TE * H; idx += 256) {
        const int e = idx >> 7, jc = idx & (H - 1);
        atomicAdd(&g_agg[s_src[e] * H + jc], s_eh[e * HS + jc]);
    }
    if (tid < TE) {
        const int src = s_src[tid];
        const float f = s_coord[tid] * s_gate[tid];
        atomicAdd(&g_cnt[src], 1.0f);
        atomicAdd(&g_delta[src * 3 + 0], s_unit[tid][0] * f);
        atomicAdd(&g_delta[src * 3 + 1], s_unit[tid][1] * f);
        atomicAdd(&g_delta[src * 3 + 2], s_unit[tid][2] * f);
    }
}

__global__ __launch_bounds__(256) void node_kernel(
    const float* __restrict__ x, const float* __restrict__ pos,
    const float* __restrict__ Wn, const float* __restrict__ bn,
    const float* __restrict__ gn, const float* __restrict__ btn,
    float* __restrict__ out)
{
    __shared__ __align__(16) float s_cat[TN * 260];
    const int tid = threadIdx.x;
    const int n0 = blockIdx.x * TN;

    for (int idx = tid; idx < TN * 64; idx += 256) {
        const int nl = idx >> 6, j4 = idx & 63;
        const int n = n0 + nl;
        float4 v = make_float4(0.f, 0.f, 0.f, 0.f);
        if (n < NN) {
            if (j4 < 32) {
                v = *(const float4*)&x[n * H + j4 * 4];
            } else {
                const float c = fmaxf(g_cnt[n], 1.f);
                const float iv = 1.f / c;
                v = *(const float4*)&g_agg[n * H + (j4 - 32) * 4];
                v.x *= iv; v.y *= iv; v.z *= iv; v.w *= iv;
            }
        }
        *(float4*)&s_cat[nl * 260 + j4 * 4] = v;
    }
    __syncthreads();

    const int jj = tid & 63, g = tid >> 6;
    const int nbv = g * 8;
    u64t accA[8], accB[8];
    #pragma unroll
    for (int e = 0; e < 8; e++) { accA[e] = 0ull; accB[e] = 0ull; }
    for (int k = 0; k < 256; k += 4) {
        const float wA0 = Wn[(k + 0) * H + jj],      wA1 = Wn[(k + 1) * H + jj];
        const float wA2 = Wn[(k + 2) * H + jj],      wA3 = Wn[(k + 3) * H + jj];
        const float wB0 = Wn[(k + 0) * H + jj + 64], wB1 = Wn[(k + 1) * H + jj + 64];
        const float wB2 = Wn[(k + 2) * H + jj + 64], wB3 = Wn[(k + 3) * H + jj + 64];
        const u64t pA0 = pack2(wA0, wA1), pA1 = pack2(wA2, wA3);
        const u64t pB0 = pack2(wB0, wB1), pB1 = pack2(wB2, wB3);
        #pragma unroll
        for (int e = 0; e < 8; e++) {
            const ulonglong2 v = *(const ulonglong2*)&s_cat[(nbv + e) * 260 + k];
            fma2(accA[e], v.x, pA0); fma2(accA[e], v.y, pA1);
            fma2(accB[e], v.x, pB0); fma2(accB[e], v.y, pB1);
        }
    }
    const float bA = bn[jj], bB = bn[jj + 64];
    __syncthreads();
    float* const s_y = s_cat;
    #pragma unroll
    for (int e = 0; e < 8; e++) {
        s_y[(nbv + e) * H + jj]      = silu_f(hadd2(accA[e]) + bA);
        s_y[(nbv + e) * H + jj + 64] = silu_f(hadd2(accB[e]) + bB);
    }
    __syncthreads();

    const int lane = tid & 31, wrp = tid >> 5;
    const float ga = gn[lane], gb = gn[lane + 32], gc = gn[lane + 64], gd = gn[lane + 96];
    const float ba = btn[lane], bb = btn[lane + 32], bcv = btn[lane + 64], bd = btn[lane + 96];
    #pragma unroll
    for (int qq = 0; qq < 4; qq++) {
        const int nl = wrp * 4 + qq;
        const int n = n0 + nl;
        float v0 = s_y[nl * H + lane], v1 = s_y[nl * H + lane + 32];
        float v2 = s_y[nl * H + lane + 64], v3 = s_y[nl * H + lane + 96];
        float s1 = v0 + v1 + v2 + v3;
        float s2 = v0 * v0 + v1 * v1 + v2 * v2 + v3 * v3;
        #pragma unroll
        for (int o = 16; o; o >>= 1) {
            s1 += __shfl_xor_sync(0xffffffffu, s1, o);
            s2 += __shfl_xor_sync(0xffffffffu, s2, o);
        }
        const float m = s1 * (1.f / 128.f);
        const float var = s2 * (1.f / 128.f) - m * m;
        const float rstd = rsqrtf(var + 1e-5f);
        if (n < NN) {
            out[n * H + lane]      = x[n * H + lane]      + (v0 - m) * rstd * ga + ba;
            out[n * H + lane + 32] = x[n * H + lane + 32] + (v1 - m) * rstd * gb + bb;
            out[n * H + lane + 64] = x[n * H + lane + 64] + (v2 - m) * rstd * gc + bcv;
            out[n * H + lane + 96] = x[n * H + lane + 96] + (v3 - m) * rstd * gd + bd;
        }
    }
    if (tid < TN) {
        const int n = n0 + tid;
        if (n < NN) {
            const float c = fmaxf(g_cnt[n], 1.f);
            const float s = 0.1f / c;
            out[NN * H + n * 3 + 0] = pos[n * 3 + 0] + s * g_delta[n * 3 + 0];
            out[NN * H + n * 3 + 1] = pos[n * 3 + 1] + s * g_delta[n * 3 + 1];
            out[NN * H + n * 3 + 2] = pos[n * 3 + 2] + s * g_delta[n * 3 + 2];
        }
    }

    // ---- re-zero scratch for next launch (globals start zeroed at load) ----
    __syncthreads();
    const float4 z4 = make_float4(0.f, 0.f, 0.f, 0.f);
    for (int idx = tid; idx < TN * 32; idx += 256) {
        const int nl = idx >> 5, j4 = idx & 31;
        const int n = n0 + nl;
        if (n < NN) *(float4*)&g_agg[n * H + j4 * 4] = z4;
    }
    if (tid < TN) {
        const int n = n0 + tid;
        if (n < NN) {
            g_cnt[n] = 0.f;
            g_delta[n * 3 + 0] = 0.f;
            g_delta[n * 3 + 1] = 0.f;
            g_delta[n * 3 + 2] = 0.f;
        }
    }
}

extern "C" void kernel_launch(void* const* d_in, const int* in_sizes, int n_in,
                              void* d_out, int out_size) {
    const float* x         = (const float*)d_in[0];
    const float* pos       = (const float*)d_in[1];
    const float* charge    = (const float*)d_in[2];
    const float* edge_attr = (const float*)d_in[3];
    const int*   edge_index= (const int*)d_in[4];
    const float* We1 = (const float*)d_in[5];
    const float* be1 = (const float*)d_in[6];
    const float* g1  = (const float*)d_in[7];
    const float* bt1 = (const float*)d_in[8];
    const float* We2 = (const float*)d_in[9];
    const float* be2 = (const float*)d_in[10];
    const float* Wn  = (const float*)d_in[11];
    const float* bn  = (const float*)d_in[12];
    const float* gn  = (const float*)d_in[13];
    const float* btn = (const float*)d_in[14];
    const float* Wc1 = (const float*)d_in[15];
    const float* bc1 = (const float*)d_in[16];
    const float* Wc2 = (const float*)d_in[17];
    const float* bc2 = (const float*)d_in[18];
    float* out = (float*)d_out;

    cudaFuncSetAttribute(edge_kernel, cudaFuncAttributeMaxDynamicSharedMemorySize, SMEM_EDGE);
    edge_kernel<<<NE / TE, 256, SMEM_EDGE>>>(x, pos, charge, edge_attr, edge_index,
                                             We1, be1, g1, bt1, We2, be2, Wc1, bc1, Wc2, bc2);
    node_kernel<<<(NN + TN - 1) / TN, 256>>>(x, pos, Wn, bn, gn, btn, out);
}